// round 13
// baseline (speedup 1.0000x reference)
#include <cuda_runtime.h>

#define L  4096
#define V  50257
#define H1 30
#define H2 50
#define G1 120   // 4*H1
#define G2 200   // 4*H2

// scratch (device globals: no allocation allowed)
__device__ float g_gx1p[L * 128];   // [t][cell*4 + gate], row padded to 128
__device__ float g_h1r [L * 32];    // layer1 hidden, row padded to 32 (1 line/row)
__device__ float g_h2p [L * 64];    // layer2 hidden, row padded to 64 (2 lines/row)
__device__ float g_wf  [G2 * H1];   // W_ih2 @ W1
__device__ float g_bf  [G2];        // W_ih2 @ bl1 + b_ih2 + b_hh2
__device__ int   g_prog;            // #h1 rows published (layer1 -> layer2)
__device__ int   g_prog2;           // #h2 rows published (layer2 -> workers)

typedef unsigned long long u64;

__device__ __forceinline__ u64 pk2(float lo, float hi) {
    u64 r; asm("mov.b64 %0, {%1, %2};" : "=l"(r) : "f"(lo), "f"(hi)); return r;
}
__device__ __forceinline__ u64 ffma2(u64 a, u64 b, u64 c) {
    u64 d; asm("fma.rn.f32x2 %0, %1, %2, %3;" : "=l"(d) : "l"(a), "l"(b), "l"(c)); return d;
}
__device__ __forceinline__ u64 fadd2(u64 a, u64 b) {
    u64 d; asm("add.rn.f32x2 %0, %1, %2;" : "=l"(d) : "l"(a), "l"(b)); return d;
}
__device__ __forceinline__ float hsum2(u64 a) {
    float x, y; asm("mov.b64 {%0, %1}, %2;" : "=f"(x), "=f"(y) : "l"(a)); return x + y;
}

__device__ __forceinline__ float fexp(float x) {
    float y; asm("ex2.approx.f32 %0, %1;" : "=f"(y) : "f"(x * 1.4426950408889634f)); return y;
}
__device__ __forceinline__ float frcp(float x) {
    float y; asm("rcp.approx.f32 %0, %1;" : "=f"(y) : "f"(x)); return y;
}
__device__ __forceinline__ float sigm(float x)   { return frcp(1.0f + fexp(-x)); }
__device__ __forceinline__ float tanh_f(float x) { return 1.0f - 2.0f * frcp(fexp(2.0f * x) + 1.0f); }

__device__ __forceinline__ int ld_acq(const int* p) {
    int v; asm volatile("ld.global.acquire.gpu.s32 %0, [%1];" : "=r"(v) : "l"(p) : "memory");
    return v;
}
__device__ __forceinline__ void st_rel(int* p, int v) {
    asm volatile("st.global.release.gpu.s32 [%0], %1;" :: "l"(p), "r"(v) : "memory");
}
// L2-coherent load (bypass non-coherent L1) for cross-CTA streamed data
__device__ __forceinline__ float4 ldcg4(const float4* p) {
    float4 v;
    asm volatile("ld.global.cg.v4.f32 {%0,%1,%2,%3}, [%4];"
                 : "=f"(v.x), "=f"(v.y), "=f"(v.z), "=f"(v.w) : "l"(p) : "memory");
    return v;
}

// ---------------------------------------------------------------------------
// K1: gx1p[t][c*4+g] = emb[x[t]] . w_ih1[g*30+c] + b_ih1 + b_hh1 (pad -> 0)
// Also resets both progress flags (runs before k_all every replay).
// ---------------------------------------------------------------------------
__global__ void k_gx1(const int* __restrict__ x, const float* __restrict__ emb,
                      const float* __restrict__ w_ih1, const float* __restrict__ b_ih1,
                      const float* __restrict__ b_hh1) {
    int idx = blockIdx.x * blockDim.x + threadIdx.x;
    if (idx == 0) { g_prog = 0; g_prog2 = 0; }
    if (idx >= L * 128) return;
    int t = idx >> 7, jj = idx & 127;
    int c = jj >> 2, g = jj & 3;
    float s = 0.0f;
    if (c < H1) {
        int j = g * H1 + c;
        const float* er = emb + (long)x[t] * H1;
        const float* wr = w_ih1 + j * H1;
        s = b_ih1[j] + b_hh1[j];
#pragma unroll
        for (int k = 0; k < H1; k++) s += er[k] * wr[k];
    }
    g_gx1p[idx] = s;
}

// ---------------------------------------------------------------------------
// K2: fuse Wf = W_ih2 @ W1, bf = W_ih2 @ bl1 + b_ih2 + b_hh2
// ---------------------------------------------------------------------------
__global__ void k_fuse(const float* __restrict__ w_ih2, const float* __restrict__ w1,
                       const float* __restrict__ bl1, const float* __restrict__ b_ih2,
                       const float* __restrict__ b_hh2) {
    int idx = blockIdx.x * blockDim.x + threadIdx.x;
    if (idx < G2 * H1) {
        int j = idx / H1, m = idx % H1;
        float s = 0.0f;
#pragma unroll
        for (int k = 0; k < H2; k++) s += w_ih2[j * H2 + k] * w1[k * H1 + m];
        g_wf[idx] = s;
    }
    if (idx < G2) {
        float s = b_ih2[idx] + b_hh2[idx];
#pragma unroll
        for (int k = 0; k < H2; k++) s += w_ih2[idx * H2 + k] * bl1[k];
        g_bf[idx] = s;
    }
}

// ---------------------------------------------------------------------------
// K3: persistent single-wave kernel, grid = 148 CTAs x 256 threads.
//   blockIdx 1  : layer1 scan (1 warp), publishes g_prog every 8 steps.
//   blockIdx 0  : layer2 scan (8 warps; warp7 = 32-slot h1 ring manager),
//                 publishes g_prog2 every 32 steps.
//   blockIdx 2+ : logits workers; t-chunk OUTER loop (paced by g_prog2),
//                 this worker's 1-2 v-chunks INNER -> tail ~ one chunk.
// ---------------------------------------------------------------------------
__global__ void __launch_bounds__(256, 1) k_all(const float* __restrict__ w_hh1,
                                                const float* __restrict__ w_hh2,
                                                const float* __restrict__ w2,
                                                const float* __restrict__ bl2,
                                                float* __restrict__ out) {
    __shared__ __align__(16) float sbuf[2048];   // worker htile 32*64; l2 ring 1024+112
    const int tid = threadIdx.x, wid = tid >> 5, lane = tid & 31;

    if (blockIdx.x == 1) {
        // ================= layer 1 : single warp =================
        if (wid != 0) return;
        float* h_sh = sbuf;
        const int c = lane;
        const bool valid = (c < H1);

        u64 w[4][15];
#pragma unroll
        for (int g = 0; g < 4; g++)
#pragma unroll
            for (int m = 0; m < 15; m++) w[g][m] = 0;
        if (valid) {
#pragma unroll
            for (int g = 0; g < 4; g++) {
                const float* row = w_hh1 + (g * H1 + c) * H1;
#pragma unroll
                for (int m = 0; m < 15; m++) w[g][m] = pk2(row[2 * m], row[2 * m + 1]);
            }
        }
        h_sh[lane] = 0.0f;
        __syncwarp();

        float cst = 0.0f;
        float4 gxbuf[2];
        gxbuf[0] = __ldg((const float4*)&g_gx1p[0 * 128 + c * 4]);
        gxbuf[1] = __ldg((const float4*)&g_gx1p[1 * 128 + c * 4]);

        for (int n = 0; n < L; n++) {
            float4 gx = gxbuf[n & 1];
            if (n + 2 < L)
                gxbuf[n & 1] = __ldg((const float4*)&g_gx1p[(n + 2) * 128 + c * 4]);

            const u64* hp = (const u64*)h_sh;
            u64 hv[15];
            {
                const ulonglong2* h2p = (const ulonglong2*)h_sh;
#pragma unroll
                for (int m = 0; m < 7; m++) { ulonglong2 t2 = h2p[m]; hv[2*m] = t2.x; hv[2*m+1] = t2.y; }
                hv[14] = hp[14];
            }
            u64 a0[4], a1[4];
#pragma unroll
            for (int g = 0; g < 4; g++) { a0[g] = 0; a1[g] = 0; }
#pragma unroll
            for (int g = 0; g < 4; g++) {
#pragma unroll
                for (int m = 0; m < 15; m += 2) a0[g] = ffma2(w[g][m], hv[m], a0[g]);
#pragma unroll
                for (int m = 1; m < 15; m += 2) a1[g] = ffma2(w[g][m], hv[m], a1[g]);
            }
            float si = gx.x + hsum2(fadd2(a0[0], a1[0]));
            float sf = gx.y + hsum2(fadd2(a0[1], a1[1]));
            float sg = gx.z + hsum2(fadd2(a0[2], a1[2]));
            float so = gx.w + hsum2(fadd2(a0[3], a1[3]));
            float ai = sigm(si), af = sigm(sf), ag = tanh_f(sg), ao = sigm(so);
            cst = af * cst + ai * ag;
            float h = valid ? ao * tanh_f(cst) : 0.0f;
            __syncwarp();
            h_sh[lane] = h;
            g_h1r[n * 32 + lane] = h;
            __syncwarp();
            if ((n & 7) == 7) {
                __threadfence();
                if (lane == 0) st_rel(&g_prog, n + 1);
            }
        }
        return;
    }

    if (blockIdx.x == 0) {
        // ================= layer 2 : 8 warps =================
        float* h1ring = sbuf;              // 32 slots x 32 floats; slot k%32 = h1[k]
        float* h2s    = sbuf + 1024;       // 2 x 56
        const int gate = lane >> 3, sub = lane & 7;
        const bool isGate = (wid < 7);
        const int cell = wid * 8 + sub;
        const bool valid = isGate && (cell < H2);

        u64 wf[15], wc[25];
        float bfv = 0.0f;
#pragma unroll
        for (int m = 0; m < 15; m++) wf[m] = 0;
#pragma unroll
        for (int m = 0; m < 25; m++) wc[m] = 0;
        if (valid) {
            int j = gate * H2 + cell;
            const float* w = g_wf + j * H1;
#pragma unroll
            for (int m = 0; m < 15; m++) wf[m] = pk2(w[2 * m], w[2 * m + 1]);
            const float* w2r = w_hh2 + j * H2;
#pragma unroll
            for (int m = 0; m < 25; m++) wc[m] = pk2(w2r[2 * m], w2r[2 * m + 1]);
            bfv = g_bf[j];
        }
        if (tid < 56) { h2s[tid] = 0.0f; h2s[56 + tid] = 0.0f; }

        // warmup: wait for 24 rows, preload ring slots 0..23 (L2-coherent loads)
        if (wid == 7) {
            if (lane == 0) { while (ld_acq(&g_prog) < 24) {} }
            __syncwarp();
#pragma unroll
            for (int q = 0; q < 6; q++) {
                int f = q * 32 + lane;           // float4 index, 192 total
                int row = f >> 3, col = f & 7;
                ((float4*)(h1ring + row * 32))[col] =
                    ldcg4((const float4*)&g_h1r[row * 32 + col * 4]);
            }
        }
        __syncthreads();

        float cst = 0.0f;
        float4 pf0, pf1;
        int pfbase = 0;
        for (int n = 0; n < L; n++) {
            if (isGate) {
                const u64* hq1 = (const u64*)(h1ring + (n & 31) * 32);  // h1[n]
                const u64* hq2 = (const u64*)(h2s + (n & 1) * 56);      // h2[n-1]
                const ulonglong2* hv1 = (const ulonglong2*)hq1;
                const ulonglong2* hv2 = (const ulonglong2*)hq2;
                u64 a0 = 0, a1 = 0, a2 = 0, a3 = 0;
#pragma unroll
                for (int m = 0; m < 7; m++) {
                    ulonglong2 hh = hv1[m];
                    a0 = ffma2(wf[2 * m],     hh.x, a0);
                    a1 = ffma2(wf[2 * m + 1], hh.y, a1);
                }
                a0 = ffma2(wf[14], hq1[14], a0);
#pragma unroll
                for (int m = 0; m < 12; m++) {
                    ulonglong2 hh = hv2[m];
                    a2 = ffma2(wc[2 * m],     hh.x, a2);
                    a3 = ffma2(wc[2 * m + 1], hh.y, a3);
                }
                a2 = ffma2(wc[24], hq2[24], a2);
                float s = bfv + hsum2(fadd2(fadd2(a0, a1), fadd2(a2, a3)));
                float act = (gate == 2) ? tanh_f(s) : sigm(s);
                float y1 = __shfl_xor_sync(0xffffffffu, act, 8);
                float y2 = __shfl_xor_sync(0xffffffffu, act, 16);
                float y3 = __shfl_xor_sync(0xffffffffu, act, 24);
                float ai, af, ag, ao;
                if      (gate == 0) { ai = act; af = y1;  ag = y2;  ao = y3;  }
                else if (gate == 1) { ai = y1;  af = act; ag = y3;  ao = y2;  }
                else if (gate == 2) { ai = y2;  af = y3;  ag = act; ao = y1;  }
                else                { ai = y3;  af = y2;  ag = y1;  ao = act; }
                cst = af * cst + ai * ag;
                float h = ao * tanh_f(cst);
                if (gate == 0 && valid) {
                    h2s[((n + 1) & 1) * 56 + cell] = h;
                    g_h2p[n * 64 + cell] = h;
                }
            } else {
                // warp 7: ring refill. Slots written at commit (iter n+4) are
                // (n+24..n+31)%32 = rows n-8..n-1, consumed >= 5 iters ago. Safe.
                int ph = n & 7;
                if (ph == 0) {
                    pfbase = n + 24;
                    if (pfbase < L) {
                        int need = pfbase + 8 <= L ? pfbase + 8 : L;
                        if (lane == 0) { while (ld_acq(&g_prog) < need) {} }
                        __syncwarp();
                        int f0 = lane, f1 = 32 + lane;
                        int r0 = pfbase + (f0 >> 3), c0 = f0 & 7;
                        int r1 = pfbase + (f1 >> 3), c1 = f1 & 7;
                        pf0 = (r0 < L) ? ldcg4((const float4*)&g_h1r[r0 * 32 + c0 * 4])
                                       : make_float4(0.f, 0.f, 0.f, 0.f);
                        pf1 = (r1 < L) ? ldcg4((const float4*)&g_h1r[r1 * 32 + c1 * 4])
                                       : make_float4(0.f, 0.f, 0.f, 0.f);
                    }
                } else if (ph == 4) {
                    if (pfbase < L) {
                        int f0 = lane, f1 = 32 + lane;
                        int r0 = pfbase + (f0 >> 3), c0 = f0 & 7;
                        int r1 = pfbase + (f1 >> 3), c1 = f1 & 7;
                        if (r0 < L) ((float4*)(h1ring + (r0 & 31) * 32))[c0] = pf0;
                        if (r1 < L) ((float4*)(h1ring + (r1 & 31) * 32))[c1] = pf1;
                    }
                }
            }
            if ((n & 31) == 31) __threadfence();
            __syncthreads();
            if ((n & 31) == 31 && tid == 0) st_rel(&g_prog2, n + 1);
        }
        return;
    }

    // ================= logits workers (blockIdx 2..147) =================
    {
        float* htile = sbuf;                       // 32 rows x 64 floats = 8KB
        const int wkr = blockIdx.x - 2;            // 0..145
        const int NWKR = 146;
        const int NVC = (V + 255) / 256;           // 197 v-chunks of 256

        int seen = 0;
        for (int t0 = 0; t0 < L; t0 += 32) {
            if (tid == 0 && seen < t0 + 32) {
                while ((seen = ld_acq(&g_prog2)) < t0 + 32) __nanosleep(1000);
            }
            __syncthreads();   // also protects htile from previous iteration's readers
            // 32 rows x 16 float4 = 512 float4, L2-coherent, line-aligned chunk
            for (int f = tid; f < 512; f += 256)
                ((float4*)htile)[f] = ldcg4((const float4*)g_h2p + t0 * 16 + f);
            __syncthreads();

            for (int vc = wkr; vc < NVC; vc += NWKR) {
                const int v = vc * 256 + tid;
                const bool active = (v < V);
                u64 wr[25];
                float bias = 0.0f;
#pragma unroll
                for (int m = 0; m < 25; m++) wr[m] = 0;
                if (active) {
                    const float* w = w2 + (long)v * H2;
#pragma unroll
                    for (int m = 0; m < 25; m++) wr[m] = pk2(w[2 * m], w[2 * m + 1]);
                    bias = bl2[v];
                }
#pragma unroll 4
                for (int tt = 0; tt < 32; tt++) {
                    const u64* hq = (const u64*)(htile + tt * 64);
                    const ulonglong2* hv = (const ulonglong2*)hq;
                    u64 a0 = 0, a1 = 0, a2 = 0, a3 = 0;
#pragma unroll
                    for (int m = 0; m < 6; m++) {
                        ulonglong2 hh = hv[2 * m];
                        a0 = ffma2(wr[4 * m],     hh.x, a0);
                        a1 = ffma2(wr[4 * m + 1], hh.y, a1);
                        ulonglong2 hh2 = hv[2 * m + 1];
                        a2 = ffma2(wr[4 * m + 2], hh2.x, a2);
                        a3 = ffma2(wr[4 * m + 3], hh2.y, a3);
                    }
                    a0 = ffma2(wr[24], hq[24], a0);
                    if (active)
                        out[(long)(t0 + tt) * V + v] =
                            hsum2(fadd2(fadd2(a0, a1), fadd2(a2, a3))) + bias;
                }
            }
        }
    }
}

// ---------------------------------------------------------------------------
extern "C" void kernel_launch(void* const* d_in, const int* in_sizes, int n_in,
                              void* d_out, int out_size) {
    const int*   x     = (const int*)  d_in[0];
    const float* emb   = (const float*)d_in[1];
    const float* w_ih1 = (const float*)d_in[2];
    const float* w_hh1 = (const float*)d_in[3];
    const float* b_ih1 = (const float*)d_in[4];
    const float* b_hh1 = (const float*)d_in[5];
    const float* w1    = (const float*)d_in[6];
    const float* bl1   = (const float*)d_in[7];
    const float* w_ih2 = (const float*)d_in[8];
    const float* w_hh2 = (const float*)d_in[9];
    const float* b_ih2 = (const float*)d_in[10];
    const float* b_hh2 = (const float*)d_in[11];
    const float* w2    = (const float*)d_in[12];
    const float* bl2   = (const float*)d_in[13];
    float* out = (float*)d_out;

    k_gx1 <<<(L * 128 + 255) / 256, 256>>>(x, emb, w_ih1, b_ih1, b_hh1);
    k_fuse<<<(G2 * H1 + 255) / 256, 256>>>(w_ih2, w1, bl1, b_ih2, b_hh2);
    k_all <<<148, 256>>>(w_hh1, w_hh2, w2, bl2, out);
}

// round 14
// speedup vs baseline: 1.3920x; 1.3920x over previous
#include <cuda_runtime.h>

#define L  4096
#define V  50257
#define H1 30
#define H2 50
#define G1 120   // 4*H1
#define G2 200   // 4*H2
#define TCHUNK 1024

// scratch (device globals: no allocation allowed)
__device__ float g_gx1p[L * 128];   // [t][cell*4 + gate], row padded to 128
__device__ float g_h1r [L * 32];    // layer1 hidden, row padded to 32 (1 line/row)
__device__ float g_h2p [L * 64];    // layer2 hidden, row padded to 64 (2 lines/row)
__device__ float g_wf  [G2 * H1];   // W_ih2 @ W1
__device__ float g_bf  [G2];        // W_ih2 @ bl1 + b_ih2 + b_hh2
__device__ float g_c1  [32];        // layer1 cell state between scan parts
__device__ float g_c2  [224];       // layer2 cell state between scan parts
__device__ int   g_prog;            // #h1 rows published (layer1 -> layer2)

typedef unsigned long long u64;

__device__ __forceinline__ u64 pk2(float lo, float hi) {
    u64 r; asm("mov.b64 %0, {%1, %2};" : "=l"(r) : "f"(lo), "f"(hi)); return r;
}
__device__ __forceinline__ u64 ffma2(u64 a, u64 b, u64 c) {
    u64 d; asm("fma.rn.f32x2 %0, %1, %2, %3;" : "=l"(d) : "l"(a), "l"(b), "l"(c)); return d;
}
__device__ __forceinline__ u64 fadd2(u64 a, u64 b) {
    u64 d; asm("add.rn.f32x2 %0, %1, %2;" : "=l"(d) : "l"(a), "l"(b)); return d;
}
__device__ __forceinline__ float hsum2(u64 a) {
    float x, y; asm("mov.b64 {%0, %1}, %2;" : "=f"(x), "=f"(y) : "l"(a)); return x + y;
}

__device__ __forceinline__ float fexp(float x) {
    float y; asm("ex2.approx.f32 %0, %1;" : "=f"(y) : "f"(x * 1.4426950408889634f)); return y;
}
__device__ __forceinline__ float frcp(float x) {
    float y; asm("rcp.approx.f32 %0, %1;" : "=f"(y) : "f"(x)); return y;
}
__device__ __forceinline__ float sigm(float x)   { return frcp(1.0f + fexp(-x)); }
__device__ __forceinline__ float tanh_f(float x) { return 1.0f - 2.0f * frcp(fexp(2.0f * x) + 1.0f); }

__device__ __forceinline__ int ld_acq(const int* p) {
    int v; asm volatile("ld.global.acquire.gpu.s32 %0, [%1];" : "=r"(v) : "l"(p) : "memory");
    return v;
}
__device__ __forceinline__ void st_rel(int* p, int v) {
    asm volatile("st.global.release.gpu.s32 [%0], %1;" :: "l"(p), "r"(v) : "memory");
}
// L2-coherent load (bypass non-coherent L1) for cross-CTA streamed data
__device__ __forceinline__ float4 ldcg4(const float4* p) {
    float4 v;
    asm volatile("ld.global.cg.v4.f32 {%0,%1,%2,%3}, [%4];"
                 : "=f"(v.x), "=f"(v.y), "=f"(v.z), "=f"(v.w) : "l"(p) : "memory");
    return v;
}

// ---------------------------------------------------------------------------
// K1: gx1p[t][c*4+g] = emb[x[t]] . w_ih1[g*30+c] + b_ih1 + b_hh1 (pad -> 0)
// Also resets the progress flag (runs once per replay, before all scan parts).
// ---------------------------------------------------------------------------
__global__ void k_gx1(const int* __restrict__ x, const float* __restrict__ emb,
                      const float* __restrict__ w_ih1, const float* __restrict__ b_ih1,
                      const float* __restrict__ b_hh1) {
    int idx = blockIdx.x * blockDim.x + threadIdx.x;
    if (idx == 0) g_prog = 0;
    if (idx >= L * 128) return;
    int t = idx >> 7, jj = idx & 127;
    int c = jj >> 2, g = jj & 3;
    float s = 0.0f;
    if (c < H1) {
        int j = g * H1 + c;
        const float* er = emb + (long)x[t] * H1;
        const float* wr = w_ih1 + j * H1;
        s = b_ih1[j] + b_hh1[j];
#pragma unroll
        for (int k = 0; k < H1; k++) s += er[k] * wr[k];
    }
    g_gx1p[idx] = s;
}

// ---------------------------------------------------------------------------
// K2: fuse Wf = W_ih2 @ W1, bf = W_ih2 @ bl1 + b_ih2 + b_hh2
// ---------------------------------------------------------------------------
__global__ void k_fuse(const float* __restrict__ w_ih2, const float* __restrict__ w1,
                       const float* __restrict__ bl1, const float* __restrict__ b_ih2,
                       const float* __restrict__ b_hh2) {
    int idx = blockIdx.x * blockDim.x + threadIdx.x;
    if (idx < G2 * H1) {
        int j = idx / H1, m = idx % H1;
        float s = 0.0f;
#pragma unroll
        for (int k = 0; k < H2; k++) s += w_ih2[j * H2 + k] * w1[k * H1 + m];
        g_wf[idx] = s;
    }
    if (idx < G2) {
        float s = b_ih2[idx] + b_hh2[idx];
#pragma unroll
        for (int k = 0; k < H2; k++) s += w_ih2[idx * H2 + k] * bl1[k];
        g_bf[idx] = s;
    }
}

// ---------------------------------------------------------------------------
// K3: scan over steps [t0, t1), two cooperating CTAs on two SMs.
//   blockIdx 1 : layer1 (1 warp), publishes g_prog every 8 steps.
//   blockIdx 0 : layer2 (warps 0-6 gates; warp 7 = 32-slot h1 ring manager,
//                batch refill every 8 steps, issue/commit split).
// Cell states carried across parts via g_c1/g_c2; h rows via g_h1r/g_h2p.
// ---------------------------------------------------------------------------
__global__ void __launch_bounds__(256, 1) k_scan(const float* __restrict__ w_hh1,
                                                 const float* __restrict__ w_hh2,
                                                 int t0, int t1) {
    __shared__ __align__(16) float sbuf[1792];
    const int tid = threadIdx.x, wid = tid >> 5, lane = tid & 31;

    if (blockIdx.x == 1) {
        // ================= layer 1 : single warp =================
        if (wid != 0) return;
        float* h_sh = sbuf;
        const int c = lane;
        const bool valid = (c < H1);

        u64 w[4][15];
#pragma unroll
        for (int g = 0; g < 4; g++)
#pragma unroll
            for (int m = 0; m < 15; m++) w[g][m] = 0;
        if (valid) {
#pragma unroll
            for (int g = 0; g < 4; g++) {
                const float* row = w_hh1 + (g * H1 + c) * H1;
#pragma unroll
                for (int m = 0; m < 15; m++) w[g][m] = pk2(row[2 * m], row[2 * m + 1]);
            }
        }
        float cst;
        if (t0 == 0) { h_sh[lane] = 0.0f; cst = 0.0f; }
        else         { h_sh[lane] = g_h1r[(t0 - 1) * 32 + lane]; cst = g_c1[lane]; }
        __syncwarp();

        float4 gxbuf[2];
        gxbuf[0] = __ldg((const float4*)&g_gx1p[(t0 + 0) * 128 + c * 4]);
        gxbuf[1] = __ldg((const float4*)&g_gx1p[(t0 + 1) * 128 + c * 4]);

        for (int n = t0; n < t1; n++) {
            float4 gx = gxbuf[n & 1];
            if (n + 2 < t1)
                gxbuf[n & 1] = __ldg((const float4*)&g_gx1p[(n + 2) * 128 + c * 4]);

            const u64* hp = (const u64*)h_sh;
            u64 hv[15];
            {
                const ulonglong2* h2p = (const ulonglong2*)h_sh;
#pragma unroll
                for (int m = 0; m < 7; m++) { ulonglong2 t2 = h2p[m]; hv[2*m] = t2.x; hv[2*m+1] = t2.y; }
                hv[14] = hp[14];
            }
            u64 a0[4], a1[4];
#pragma unroll
            for (int g = 0; g < 4; g++) { a0[g] = 0; a1[g] = 0; }
#pragma unroll
            for (int g = 0; g < 4; g++) {
#pragma unroll
                for (int m = 0; m < 15; m += 2) a0[g] = ffma2(w[g][m], hv[m], a0[g]);
#pragma unroll
                for (int m = 1; m < 15; m += 2) a1[g] = ffma2(w[g][m], hv[m], a1[g]);
            }
            float si = gx.x + hsum2(fadd2(a0[0], a1[0]));
            float sf = gx.y + hsum2(fadd2(a0[1], a1[1]));
            float sg = gx.z + hsum2(fadd2(a0[2], a1[2]));
            float so = gx.w + hsum2(fadd2(a0[3], a1[3]));
            float ai = sigm(si), af = sigm(sf), ag = tanh_f(sg), ao = sigm(so);
            cst = af * cst + ai * ag;
            float h = valid ? ao * tanh_f(cst) : 0.0f;
            __syncwarp();
            h_sh[lane] = h;
            g_h1r[n * 32 + lane] = h;
            __syncwarp();
            if ((n & 7) == 7) {
                __threadfence();
                if (lane == 0) st_rel(&g_prog, n + 1);
            }
        }
        g_c1[lane] = cst;
        return;
    }

    // ================= layer 2 : 8 warps =================
    {
        float* h1ring = sbuf;              // 32 slots x 32 floats; slot k%32 = h1[k]
        float* h2s    = sbuf + 1024;       // 2 x 56
        const int gate = lane >> 3, sub = lane & 7;
        const bool isGate = (wid < 7);
        const int cell = wid * 8 + sub;
        const bool valid = isGate && (cell < H2);

        u64 wf[15], wc[25];
        float bfv = 0.0f;
#pragma unroll
        for (int m = 0; m < 15; m++) wf[m] = 0;
#pragma unroll
        for (int m = 0; m < 25; m++) wc[m] = 0;
        if (valid) {
            int j = gate * H2 + cell;
            const float* w = g_wf + j * H1;
#pragma unroll
            for (int m = 0; m < 15; m++) wf[m] = pk2(w[2 * m], w[2 * m + 1]);
            const float* w2r = w_hh2 + j * H2;
#pragma unroll
            for (int m = 0; m < 25; m++) wc[m] = pk2(w2r[2 * m], w2r[2 * m + 1]);
            bfv = g_bf[j];
        }
        float cst = 0.0f;
        if (t0 == 0) {
            if (tid < 56) { h2s[tid] = 0.0f; h2s[56 + tid] = 0.0f; }
        } else {
            // slot (t0 & 1) == 0 must hold h2[t0-1]  (t0 is a multiple of 1024)
            if (tid < 56) { h2s[tid] = g_h2p[(t0 - 1) * 64 + tid]; h2s[56 + tid] = 0.0f; }
            if (wid < 7) cst = g_c2[wid * 32 + lane];
        }

        // warmup: wait for rows t0..t0+23, preload ring (L2-coherent loads)
        if (wid == 7) {
            if (lane == 0) { while (ld_acq(&g_prog) < t0 + 24) {} }
            __syncwarp();
#pragma unroll
            for (int q = 0; q < 6; q++) {
                int f = q * 32 + lane;           // float4 index, 192 total
                int row = t0 + (f >> 3), col = f & 7;
                ((float4*)(h1ring + (row & 31) * 32))[col] =
                    ldcg4((const float4*)&g_h1r[row * 32 + col * 4]);
            }
        }
        __syncthreads();

        float4 pf0, pf1;
        int pfbase = 0;
        bool pfvalid = false;
        for (int n = t0; n < t1; n++) {
            if (isGate) {
                const u64* hq1 = (const u64*)(h1ring + (n & 31) * 32);  // h1[n]
                const u64* hq2 = (const u64*)(h2s + (n & 1) * 56);      // h2[n-1]
                const ulonglong2* hv1 = (const ulonglong2*)hq1;
                const ulonglong2* hv2 = (const ulonglong2*)hq2;
                u64 a0 = 0, a1 = 0, a2 = 0, a3 = 0;
#pragma unroll
                for (int m = 0; m < 7; m++) {
                    ulonglong2 hh = hv1[m];
                    a0 = ffma2(wf[2 * m],     hh.x, a0);
                    a1 = ffma2(wf[2 * m + 1], hh.y, a1);
                }
                a0 = ffma2(wf[14], hq1[14], a0);
#pragma unroll
                for (int m = 0; m < 12; m++) {
                    ulonglong2 hh = hv2[m];
                    a2 = ffma2(wc[2 * m],     hh.x, a2);
                    a3 = ffma2(wc[2 * m + 1], hh.y, a3);
                }
                a2 = ffma2(wc[24], hq2[24], a2);
                float s = bfv + hsum2(fadd2(fadd2(a0, a1), fadd2(a2, a3)));
                float act = (gate == 2) ? tanh_f(s) : sigm(s);
                float y1 = __shfl_xor_sync(0xffffffffu, act, 8);
                float y2 = __shfl_xor_sync(0xffffffffu, act, 16);
                float y3 = __shfl_xor_sync(0xffffffffu, act, 24);
                float ai, af, ag, ao;
                if      (gate == 0) { ai = act; af = y1;  ag = y2;  ao = y3;  }
                else if (gate == 1) { ai = y1;  af = act; ag = y3;  ao = y2;  }
                else if (gate == 2) { ai = y2;  af = y3;  ag = act; ao = y1;  }
                else                { ai = y3;  af = y2;  ag = y1;  ao = act; }
                cst = af * cst + ai * ag;
                float h = ao * tanh_f(cst);
                if (gate == 0 && valid) {
                    h2s[((n + 1) & 1) * 56 + cell] = h;
                    g_h2p[n * 64 + cell] = h;
                }
            } else {
                // warp 7: ring refill. Commit (iter n+4) writes slots of rows
                // n-8..n-1, consumed >= 5 iterations earlier. Race-free.
                int ph = n & 7;
                if (ph == 0) {
                    pfbase = n + 24;
                    pfvalid = (pfbase < t1);
                    if (pfvalid) {
                        int need = pfbase + 8 <= t1 ? pfbase + 8 : t1;
                        if (lane == 0) { while (ld_acq(&g_prog) < need) {} }
                        __syncwarp();
                        int f0 = lane, f1 = 32 + lane;
                        int r0 = pfbase + (f0 >> 3), c0 = f0 & 7;
                        int r1 = pfbase + (f1 >> 3), c1 = f1 & 7;
                        pf0 = (r0 < t1) ? ldcg4((const float4*)&g_h1r[r0 * 32 + c0 * 4])
                                        : make_float4(0.f, 0.f, 0.f, 0.f);
                        pf1 = (r1 < t1) ? ldcg4((const float4*)&g_h1r[r1 * 32 + c1 * 4])
                                        : make_float4(0.f, 0.f, 0.f, 0.f);
                    }
                } else if (ph == 4) {
                    if (pfvalid) {
                        int f0 = lane, f1 = 32 + lane;
                        int r0 = pfbase + (f0 >> 3), c0 = f0 & 7;
                        int r1 = pfbase + (f1 >> 3), c1 = f1 & 7;
                        if (r0 < t1) ((float4*)(h1ring + (r0 & 31) * 32))[c0] = pf0;
                        if (r1 < t1) ((float4*)(h1ring + (r1 & 31) * 32))[c1] = pf1;
                    }
                }
            }
            __syncthreads();
        }
        if (wid < 7) g_c2[wid * 32 + lane] = cst;
    }
}

// ---------------------------------------------------------------------------
// K4: out[t][v] = h2[t] . w2[v] + bl2[v] for t in [tbase + by*256, +256)
// grid: (ceil(V/128), 4), block 128.  (f32x2 FMA, float4 h-tile copies)
// ---------------------------------------------------------------------------
__global__ void k_out(const float* __restrict__ w2, const float* __restrict__ bl2,
                      float* __restrict__ out, int tbase) {
    __shared__ __align__(16) float h_sh[32 * 64];
    int v = blockIdx.x * blockDim.x + threadIdx.x;
    bool active = (v < V);

    u64 wr[25];
    float bias = 0.0f;
    if (active) {
        const float* w = w2 + (long)v * H2;
#pragma unroll
        for (int m = 0; m < 25; m++) wr[m] = pk2(w[2 * m], w[2 * m + 1]);
        bias = bl2[v];
    }

    int tbeg = tbase + blockIdx.y * 256;
    int tend = tbeg + 256;
    for (int t0 = tbeg; t0 < tend; t0 += 32) {
        __syncthreads();
        // 32 rows x 16 float4 = 512 float4, 4 per thread
        for (int f = threadIdx.x; f < 512; f += blockDim.x)
            ((float4*)h_sh)[f] = __ldg((const float4*)(g_h2p + t0 * 64) + f);
        __syncthreads();
#pragma unroll 4
        for (int tt = 0; tt < 32; tt++) {
            const u64* hq = (const u64*)(h_sh + tt * 64);
            const ulonglong2* hv = (const ulonglong2*)hq;
            u64 a0 = 0, a1 = 0, a2 = 0, a3 = 0;
#pragma unroll
            for (int m = 0; m < 6; m++) {
                ulonglong2 hh = hv[2 * m];
                a0 = ffma2(wr[4 * m],     hh.x, a0);
                a1 = ffma2(wr[4 * m + 1], hh.y, a1);
                ulonglong2 hh2 = hv[2 * m + 1];
                a2 = ffma2(wr[4 * m + 2], hh2.x, a2);
                a3 = ffma2(wr[4 * m + 3], hh2.y, a3);
            }
            a0 = ffma2(wr[24], hq[24], a0);
            if (active)
                out[(long)(t0 + tt) * V + v] =
                    hsum2(fadd2(fadd2(a0, a1), fadd2(a2, a3))) + bias;
        }
    }
}

// ---------------------------------------------------------------------------
extern "C" void kernel_launch(void* const* d_in, const int* in_sizes, int n_in,
                              void* d_out, int out_size) {
    const int*   x     = (const int*)  d_in[0];
    const float* emb   = (const float*)d_in[1];
    const float* w_ih1 = (const float*)d_in[2];
    const float* w_hh1 = (const float*)d_in[3];
    const float* b_ih1 = (const float*)d_in[4];
    const float* b_hh1 = (const float*)d_in[5];
    const float* w1    = (const float*)d_in[6];
    const float* bl1   = (const float*)d_in[7];
    const float* w_ih2 = (const float*)d_in[8];
    const float* w_hh2 = (const float*)d_in[9];
    const float* b_ih2 = (const float*)d_in[10];
    const float* b_hh2 = (const float*)d_in[11];
    const float* w2    = (const float*)d_in[12];
    const float* bl2   = (const float*)d_in[13];
    float* out = (float*)d_out;

    // one-time stream/event setup (no device memory involved)
    static cudaStream_t s2 = nullptr;
    static cudaEvent_t evS[4], evJ;
    if (s2 == nullptr) {
        cudaStreamCreateWithFlags(&s2, cudaStreamNonBlocking);
        for (int i = 0; i < 4; i++)
            cudaEventCreateWithFlags(&evS[i], cudaEventDisableTiming);
        cudaEventCreateWithFlags(&evJ, cudaEventDisableTiming);
    }

    k_gx1 <<<(L * 128 + 255) / 256, 256>>>(x, emb, w_ih1, b_ih1, b_hh1);
    k_fuse<<<(G2 * H1 + 255) / 256, 256>>>(w_ih2, w1, bl1, b_ih2, b_hh2);

    dim3 gout((V + 127) / 128, 4);
    for (int p = 0; p < 4; p++) {
        int t0 = p * TCHUNK, t1 = t0 + TCHUNK;
        k_scan<<<2, 256>>>(w_hh1, w_hh2, t0, t1);
        cudaEventRecord(evS[p], 0);
        cudaStreamWaitEvent(s2, evS[p], 0);
        k_out<<<gout, 128, 0, s2>>>(w2, bl2, out, t0);
    }
    cudaEventRecord(evJ, s2);
    cudaStreamWaitEvent(0, evJ, 0);
}